// round 5
// baseline (speedup 1.0000x reference)
#include <cuda_runtime.h>

#define BB 2048
#define TT 1024

// ============================ Fused decoder ================================
// One CTA (256 threads) per batch row b.
// Phase A: v[t] = Wz @ z[b,t-1]  (t>=1), v[0] = init_states[b]  -> shared mem
//   8 lanes cooperate per z row (warp load = 512B contiguous);
//   4-shuffle split reduce: px in lanes c8<4, py in lanes c8>=4.
// Phase B: chunked affine scan (4 timesteps/thread); chunk-scanned values are
//   parked back in smem (register diet -> 8 CTAs/SM), carry fixup on reload.
__global__ __launch_bounds__(256, 8)
void fused_decoder_kernel(const float* __restrict__ init_states,
                          const float* __restrict__ z,
                          const float* __restrict__ W,
                          float* __restrict__ out) {
    __shared__ alignas(16) float2 sv[TT];   // 8KB: per-timestep vectors
    __shared__ float2 agg[8];               // per-warp scan aggregates
    __shared__ float  sPW[5][4];            // A^4, A^8, A^16, A^32, A^64
    __shared__ float4 sW0[8], sW1[8];       // Wz rows

    const int b    = blockIdx.x;
    const int tid  = threadIdx.x;
    const int lane = tid & 31;
    const int warp = tid >> 5;

    if (tid < 64) {
        const int rr = tid >> 5, c = tid & 31;
        reinterpret_cast<float*>(rr ? sW1 : sW0)[c] = W[rr * 34 + 2 + c];
    }
    __syncthreads();

    // ---------------- Phase A: dot products into shared ----------------
    {
        const int g  = lane >> 3;   // row within 4-row group
        const int c8 = lane & 7;    // 16B column slice
        const float4 w0 = sW0[c8];
        const float4 w1 = sW1[c8];
        const float4* z4 = reinterpret_cast<const float4*>(z) + (size_t)b * TT * 8;
        const int base = warp * 128;   // each warp owns 128 consecutive z rows

        #pragma unroll 8
        for (int j = 0; j < 32; ++j) {
            const int r = base + j * 4 + g;
            const float4 q = __ldcs(&z4[r * 8 + c8]);
            float px = fmaf(q.x, w0.x, fmaf(q.y, w0.y, fmaf(q.z, w0.z, q.w * w0.w)));
            float py = fmaf(q.x, w1.x, fmaf(q.y, w1.y, fmaf(q.z, w1.z, q.w * w1.w)));
            // split reduce over the 8-lane octet: 4 shuffles instead of 6
            float u  = (c8 < 4) ? px : py;
            float w_ = (c8 < 4) ? py : px;
            u += __shfl_xor_sync(0xffffffffu, w_, 4);
            u += __shfl_xor_sync(0xffffffffu, u, 1);
            u += __shfl_xor_sync(0xffffffffu, u, 2);
            const float pv = __shfl_xor_sync(0xffffffffu, u, 4);
            if (c8 == 0 && r + 1 < TT) sv[r + 1] = make_float2(u, pv);
        }
    }
    if (tid == 0) sv[0] = make_float2(init_states[2 * b], init_states[2 * b + 1]);
    __syncthreads();

    // ---------------- Phase B: chunked affine scan ----------------
    const float a00 = __ldg(&W[0]),  a01 = __ldg(&W[1]);
    const float a10 = __ldg(&W[34]), a11 = __ldg(&W[35]);

    float4* svp = reinterpret_cast<float4*>(sv) + tid * 2;

    // serial inclusive scan of the 4-chunk; park results back into smem
    float2 s;
    {
        const float4 c0 = svp[0], c1 = svp[1];
        s = make_float2(c0.x, c0.y);
        float s1x = fmaf(a00, s.x, fmaf(a01, s.y, c0.z));
        float s1y = fmaf(a10, s.x, fmaf(a11, s.y, c0.w));
        float s2x = fmaf(a00, s1x, fmaf(a01, s1y, c1.x));
        float s2y = fmaf(a10, s1x, fmaf(a11, s1y, c1.y));
        float s3x = fmaf(a00, s2x, fmaf(a01, s2y, c1.z));
        float s3y = fmaf(a10, s2x, fmaf(a11, s2y, c1.w));
        svp[0] = make_float4(s.x, s.y, s1x, s1y);
        svp[1] = make_float4(s2x, s2y, s3x, s3y);
        s = make_float2(s3x, s3y);
    }

    // A -> A^4 (2 squarings)
    float p00 = a00, p01 = a01, p10 = a10, p11 = a11;
    #pragma unroll
    for (int i = 0; i < 2; ++i) {
        float q00 = p00*p00 + p01*p10, q01 = p00*p01 + p01*p11;
        float q10 = p10*p00 + p11*p10, q11 = p10*p01 + p11*p11;
        p00 = q00; p01 = q01; p10 = q10; p11 = q11;
    }

    // warp shuffle scan of chunk aggregates; powers A^(4*2^d)
    float2 x = s;
    #pragma unroll
    for (int d = 0; d < 5; ++d) {
        if (tid == 0) { sPW[d][0] = p00; sPW[d][1] = p01; sPW[d][2] = p10; sPW[d][3] = p11; }
        const int o = 1 << d;
        float ox = __shfl_up_sync(0xffffffffu, x.x, o);
        float oy = __shfl_up_sync(0xffffffffu, x.y, o);
        if (lane >= o) {
            x.x = fmaf(p00, ox, fmaf(p01, oy, x.x));
            x.y = fmaf(p10, ox, fmaf(p11, oy, x.y));
        }
        float q00 = p00*p00 + p01*p10, q01 = p00*p01 + p01*p11;
        float q10 = p10*p00 + p11*p10, q11 = p10*p01 + p11*p11;
        p00 = q00; p01 = q01; p10 = q10; p11 = q11;
    }
    // p = A^128 (one warp segment)

    if (lane == 31) agg[warp] = x;
    __syncthreads();   // publishes agg and sPW (and parked chunk scans)

    // prefix over earlier warps (combine power A^128), <=7 serial steps
    float2 P = make_float2(0.f, 0.f);
    for (int u = 0; u < warp; ++u) {
        float nx = fmaf(p00, P.x, fmaf(p01, P.y, agg[u].x));
        float ny = fmaf(p10, P.x, fmaf(p11, P.y, agg[u].y));
        P.x = nx; P.y = ny;
    }

    // exclusive lane prefix within warp
    float Ex = __shfl_up_sync(0xffffffffu, x.x, 1);
    float Ey = __shfl_up_sync(0xffffffffu, x.y, 1);
    if (lane == 0) { Ex = 0.f; Ey = 0.f; }

    // M = A^(4*lane) from shared power table
    float m00 = 1.f, m01 = 0.f, m10 = 0.f, m11 = 1.f;
    #pragma unroll
    for (int d = 0; d < 5; ++d) {
        if (lane & (1 << d)) {
            const float w0 = sPW[d][0], w1 = sPW[d][1];
            const float w2 = sPW[d][2], w3 = sPW[d][3];
            float n00 = w0*m00 + w1*m10, n01 = w0*m01 + w1*m11;
            float n10 = w2*m00 + w3*m10, n11 = w2*m01 + w3*m11;
            m00 = n00; m01 = n01; m10 = n10; m11 = n11;
        }
    }
    const float bx = Ex + m00 * P.x + m01 * P.y;
    const float by = Ey + m10 * P.x + m11 * P.y;

    // carry fixup on reload + coalesced streaming store
    float cx = fmaf(a00, bx, a01 * by);
    float cy = fmaf(a10, bx, a11 * by);
    const float4 r0 = svp[0], r1 = svp[1];
    float4 o0, o1;
    o0.x = r0.x + cx;  o0.y = r0.y + cy;
    { float nx = fmaf(a00, cx, a01 * cy), ny = fmaf(a10, cx, a11 * cy); cx = nx; cy = ny; }
    o0.z = r0.z + cx;  o0.w = r0.w + cy;
    { float nx = fmaf(a00, cx, a01 * cy), ny = fmaf(a10, cx, a11 * cy); cx = nx; cy = ny; }
    o1.x = r1.x + cx;  o1.y = r1.y + cy;
    { float nx = fmaf(a00, cx, a01 * cy), ny = fmaf(a10, cx, a11 * cy); cx = nx; cy = ny; }
    o1.z = r1.z + cx;  o1.w = r1.w + cy;

    float4* op = reinterpret_cast<float4*>(out) + ((size_t)b * TT / 2) + tid * 2;
    __stcs(op,     o0);
    __stcs(op + 1, o1);
}

extern "C" void kernel_launch(void* const* d_in, const int* in_sizes, int n_in,
                              void* d_out, int out_size) {
    const float* init_states = (const float*)d_in[0];
    const float* z           = (const float*)d_in[1];
    const float* W           = (const float*)d_in[2];
    float*       out         = (float*)d_out;

    fused_decoder_kernel<<<BB, 256>>>(init_states, z, W, out);
}

// round 6
// speedup vs baseline: 1.0345x; 1.0345x over previous
#include <cuda_runtime.h>
#include <cstdint>

#define BB  2048
#define TT  1024
#define RPS 128           // z rows per pipeline stage
#define NSTG (TT / RPS)   // 8 stages per batch row

__device__ __forceinline__ uint32_t s2u(const void* p) {
    return (uint32_t)__cvta_generic_to_shared(p);
}

// ============================ Fused decoder ================================
// One CTA (256 threads) per batch row b.
// Phase A: z streamed through a 2-slot cp.async smem ring (16KB/stage, 2 stages
//   in flight => deep MLP with zero register payload). Dot products computed
//   from staged smem (conflict-free octet reads + 4-shuffle reduce) into sv.
// Phase B: chunked affine scan (4 timesteps/thread), combine x <- A^len*xl + x.
__global__ __launch_bounds__(256, 4)
void fused_decoder_kernel(const float* __restrict__ init_states,
                          const float* __restrict__ z,
                          const float* __restrict__ W,
                          float* __restrict__ out) {
    __shared__ alignas(16) float  zstage[2][RPS * 32];  // 2 x 16KB ring
    __shared__ alignas(16) float2 sv[TT];               // 8KB per-timestep vectors
    __shared__ float2 agg[8];
    __shared__ float  sPW[5][4];
    __shared__ float4 sW0[8], sW1[8];

    const int b    = blockIdx.x;
    const int tid  = threadIdx.x;
    const int lane = tid & 31;
    const int warp = tid >> 5;

    if (tid < 64) {
        const int rr = tid >> 5, c = tid & 31;
        reinterpret_cast<float*>(rr ? sW1 : sW0)[c] = W[rr * 34 + 2 + c];
    }
    if (tid == 0) sv[0] = make_float2(init_states[2 * b], init_states[2 * b + 1]);

    const float4* zbase = reinterpret_cast<const float4*>(z) + (size_t)b * (TT * 8);

    // issue one 16KB stage: 1024 float4s, 4 per thread, fully coalesced
    auto issue = [&](int s) {
        const float4* src = zbase + s * (RPS * 8) + tid;
        const uint32_t dst = s2u(&zstage[s & 1][0]) + (uint32_t)tid * 16u;
        #pragma unroll
        for (int k = 0; k < 4; ++k) {
            asm volatile("cp.async.cg.shared.global [%0], [%1], 16;"
                         :: "r"(dst + k * 256 * 16), "l"(src + k * 256));
        }
    };

    issue(0);
    asm volatile("cp.async.commit_group;" ::: "memory");
    issue(1);
    asm volatile("cp.async.commit_group;" ::: "memory");

    __syncthreads();                      // publish sW0/sW1
    const int g  = lane >> 3;             // row within 4-row group
    const int c8 = lane & 7;              // 16B column slice
    const float4 w0 = sW0[c8];
    const float4 w1 = sW1[c8];

    // ---------------- Phase A: pipelined stages ----------------
    for (int s = 0; s < NSTG; ++s) {
        asm volatile("cp.async.wait_group 1;" ::: "memory");  // stage s complete
        __syncthreads();

        const float* st = zstage[s & 1];
        #pragma unroll
        for (int j = 0; j < 4; ++j) {
            const int rl = warp * 16 + j * 4 + g;             // local row 0..127
            const float4 q = *reinterpret_cast<const float4*>(&st[rl * 32 + c8 * 4]);
            float px = fmaf(q.x, w0.x, fmaf(q.y, w0.y, fmaf(q.z, w0.z, q.w * w0.w)));
            float py = fmaf(q.x, w1.x, fmaf(q.y, w1.y, fmaf(q.z, w1.z, q.w * w1.w)));
            // split reduce over the 8-lane octet: 4 shuffles
            float u  = (c8 < 4) ? px : py;
            float w_ = (c8 < 4) ? py : px;
            u += __shfl_xor_sync(0xffffffffu, w_, 4);
            u += __shfl_xor_sync(0xffffffffu, u, 1);
            u += __shfl_xor_sync(0xffffffffu, u, 2);
            const float pv = __shfl_xor_sync(0xffffffffu, u, 4);
            const int r = s * RPS + rl;
            if (c8 == 0 && r + 1 < TT) sv[r + 1] = make_float2(u, pv);
        }
        __syncthreads();                  // stage s fully consumed before reuse

        if (s + 2 < NSTG) issue(s + 2);
        asm volatile("cp.async.commit_group;" ::: "memory");  // keep group count uniform
    }
    // last loop iteration's __syncthreads() ordered all sv writes before here.

    // ---------------- Phase B: chunked affine scan ----------------
    const float a00 = __ldg(&W[0]),  a01 = __ldg(&W[1]);
    const float a10 = __ldg(&W[34]), a11 = __ldg(&W[35]);

    float4* svp = reinterpret_cast<float4*>(sv) + tid * 2;

    // serial inclusive scan of the 4-chunk; park results back into smem
    float2 s2;
    {
        const float4 c0 = svp[0], c1 = svp[1];
        s2 = make_float2(c0.x, c0.y);
        float s1x = fmaf(a00, s2.x, fmaf(a01, s2.y, c0.z));
        float s1y = fmaf(a10, s2.x, fmaf(a11, s2.y, c0.w));
        float s2x = fmaf(a00, s1x, fmaf(a01, s1y, c1.x));
        float s2y = fmaf(a10, s1x, fmaf(a11, s1y, c1.y));
        float s3x = fmaf(a00, s2x, fmaf(a01, s2y, c1.z));
        float s3y = fmaf(a10, s2x, fmaf(a11, s2y, c1.w));
        svp[0] = make_float4(s2.x, s2.y, s1x, s1y);
        svp[1] = make_float4(s2x, s2y, s3x, s3y);
        s2 = make_float2(s3x, s3y);
    }

    // A -> A^4 (2 squarings)
    float p00 = a00, p01 = a01, p10 = a10, p11 = a11;
    #pragma unroll
    for (int i = 0; i < 2; ++i) {
        float q00 = p00*p00 + p01*p10, q01 = p00*p01 + p01*p11;
        float q10 = p10*p00 + p11*p10, q11 = p10*p01 + p11*p11;
        p00 = q00; p01 = q01; p10 = q10; p11 = q11;
    }

    // warp shuffle scan of chunk aggregates; powers A^(4*2^d)
    float2 x = s2;
    #pragma unroll
    for (int d = 0; d < 5; ++d) {
        if (tid == 0) { sPW[d][0] = p00; sPW[d][1] = p01; sPW[d][2] = p10; sPW[d][3] = p11; }
        const int o = 1 << d;
        float ox = __shfl_up_sync(0xffffffffu, x.x, o);
        float oy = __shfl_up_sync(0xffffffffu, x.y, o);
        if (lane >= o) {
            x.x = fmaf(p00, ox, fmaf(p01, oy, x.x));
            x.y = fmaf(p10, ox, fmaf(p11, oy, x.y));
        }
        float q00 = p00*p00 + p01*p10, q01 = p00*p01 + p01*p11;
        float q10 = p10*p00 + p11*p10, q11 = p10*p01 + p11*p11;
        p00 = q00; p01 = q01; p10 = q10; p11 = q11;
    }
    // p = A^128 (one warp segment)

    if (lane == 31) agg[warp] = x;
    __syncthreads();   // publishes agg, sPW, parked chunk scans

    // prefix over earlier warps (combine power A^128), <=7 serial steps
    float2 P = make_float2(0.f, 0.f);
    for (int u = 0; u < warp; ++u) {
        float nx = fmaf(p00, P.x, fmaf(p01, P.y, agg[u].x));
        float ny = fmaf(p10, P.x, fmaf(p11, P.y, agg[u].y));
        P.x = nx; P.y = ny;
    }

    // exclusive lane prefix within warp
    float Ex = __shfl_up_sync(0xffffffffu, x.x, 1);
    float Ey = __shfl_up_sync(0xffffffffu, x.y, 1);
    if (lane == 0) { Ex = 0.f; Ey = 0.f; }

    // M = A^(4*lane) from shared power table
    float m00 = 1.f, m01 = 0.f, m10 = 0.f, m11 = 1.f;
    #pragma unroll
    for (int d = 0; d < 5; ++d) {
        if (lane & (1 << d)) {
            const float v0 = sPW[d][0], v1 = sPW[d][1];
            const float v2 = sPW[d][2], v3 = sPW[d][3];
            float n00 = v0*m00 + v1*m10, n01 = v0*m01 + v1*m11;
            float n10 = v2*m00 + v3*m10, n11 = v2*m01 + v3*m11;
            m00 = n00; m01 = n01; m10 = n10; m11 = n11;
        }
    }
    const float bx = Ex + m00 * P.x + m01 * P.y;
    const float by = Ey + m10 * P.x + m11 * P.y;

    // carry fixup on reload + coalesced streaming store
    float cx = fmaf(a00, bx, a01 * by);
    float cy = fmaf(a10, bx, a11 * by);
    const float4 r0 = svp[0], r1 = svp[1];
    float4 o0, o1;
    o0.x = r0.x + cx;  o0.y = r0.y + cy;
    { float nx = fmaf(a00, cx, a01 * cy), ny = fmaf(a10, cx, a11 * cy); cx = nx; cy = ny; }
    o0.z = r0.z + cx;  o0.w = r0.w + cy;
    { float nx = fmaf(a00, cx, a01 * cy), ny = fmaf(a10, cx, a11 * cy); cx = nx; cy = ny; }
    o1.x = r1.x + cx;  o1.y = r1.y + cy;
    { float nx = fmaf(a00, cx, a01 * cy), ny = fmaf(a10, cx, a11 * cy); cx = nx; cy = ny; }
    o1.z = r1.z + cx;  o1.w = r1.w + cy;

    float4* op = reinterpret_cast<float4*>(out) + ((size_t)b * TT / 2) + tid * 2;
    __stcs(op,     o0);
    __stcs(op + 1, o1);
}

extern "C" void kernel_launch(void* const* d_in, const int* in_sizes, int n_in,
                              void* d_out, int out_size) {
    const float* init_states = (const float*)d_in[0];
    const float* z           = (const float*)d_in[1];
    const float* W           = (const float*)d_in[2];
    float*       out         = (float*)d_out;

    fused_decoder_kernel<<<BB, 256>>>(init_states, z, W, out);
}

// round 7
// speedup vs baseline: 1.0763x; 1.0404x over previous
#include <cuda_runtime.h>
#include <cstdint>

#define BB  2048
#define TT  1024
#define NW  8      // warps per CTA
#define NST 8      // stages per warp (16 rows each)

__device__ __forceinline__ uint32_t s2u(const void* p) {
    return (uint32_t)__cvta_generic_to_shared(p);
}

// ============================ Fused decoder ================================
// One CTA (256 threads) per batch row b.
// Phase A: each warp owns 128 consecutive z rows, streamed through its own
//   private 2-slot cp.async ring (2KB chunks of 16 rows). XOR-swizzled layout
//   ((j+row)&7) makes writes and reads bank-conflict free. 2 lanes per row,
//   2 shuffles per 16 rows. Warp-local sync only.
// Phase B: chunked affine scan (4 timesteps/thread), combine x <- A^len*xl + x.
__global__ __launch_bounds__(256, 5)
void fused_decoder_kernel(const float* __restrict__ init_states,
                          const float* __restrict__ z,
                          const float* __restrict__ W,
                          float* __restrict__ out) {
    __shared__ alignas(16) float4 zring[NW][2][128];  // 32KB: per-warp 2-slot rings
    __shared__ alignas(16) float2 sv[TT];             // 8KB per-timestep vectors
    __shared__ float2 agg[8];
    __shared__ float  sPW[5][4];
    __shared__ float4 sW0[8], sW1[8];

    const int b    = blockIdx.x;
    const int tid  = threadIdx.x;
    const int lane = tid & 31;
    const int warp = tid >> 5;

    if (tid < 64) {
        const int rr = tid >> 5, c = tid & 31;
        reinterpret_cast<float*>(rr ? sW1 : sW0)[c] = W[rr * 34 + 2 + c];
    }
    if (tid == 0) sv[0] = make_float2(init_states[2 * b], init_states[2 * b + 1]);

    // ---- precomputed swizzled offsets (lane-only, hoisted) ----
    int woff[4], roff[4];
    #pragma unroll
    for (int k = 0; k < 4; ++k) {            // write: linear chunk float4 i2
        const int i2 = lane + 32 * k;
        const int row = i2 >> 3, j = i2 & 7;
        woff[k] = row * 8 + ((j + row) & 7);
    }
    const int rrow = lane >> 1;              // local row this lane computes
    const int half = (lane & 1) * 4;         // chunk half: 0..3 or 4..7
    #pragma unroll
    for (int k = 0; k < 4; ++k) {
        const int c = half + k;
        roff[k] = rrow * 8 + ((c + rrow) & 7);
    }

    const float4* zw = reinterpret_cast<const float4*>(z)
                       + ((size_t)b * TT + warp * 128) * 8;
    const uint32_t slotu[2] = { s2u(&zring[warp][0][0]), s2u(&zring[warp][1][0]) };

    auto issue = [&](int s) {                // one 2KB chunk: 4 cp.async / lane
        const float4* src = zw + s * 128 + lane;
        const uint32_t dst = slotu[s & 1];
        #pragma unroll
        for (int k = 0; k < 4; ++k) {
            asm volatile("cp.async.cg.shared.global [%0], [%1], 16;"
                         :: "r"(dst + (uint32_t)woff[k] * 16u), "l"(src + 32 * k));
        }
    };

    issue(0);
    asm volatile("cp.async.commit_group;" ::: "memory");
    issue(1);
    asm volatile("cp.async.commit_group;" ::: "memory");

    __syncthreads();                         // publish sW0/sW1 (once)

    // ---------------- Phase A: per-warp pipelined stages ----------------
    for (int s = 0; s < NST; ++s) {
        asm volatile("cp.async.wait_group 1;" ::: "memory");
        __syncwarp();
        const float4* slot = &zring[warp][s & 1][0];

        float px = 0.f, py = 0.f;
        #pragma unroll
        for (int k = 0; k < 4; ++k) {
            const float4 q  = slot[roff[k]];
            const float4 w0 = sW0[half + k];
            const float4 w1 = sW1[half + k];
            px = fmaf(q.x, w0.x, fmaf(q.y, w0.y, fmaf(q.z, w0.z, fmaf(q.w, w0.w, px))));
            py = fmaf(q.x, w1.x, fmaf(q.y, w1.y, fmaf(q.z, w1.z, fmaf(q.w, w1.w, py))));
        }
        // pair reduce: even lane holds px-half, odd holds py-half
        float u  = (lane & 1) ? py : px;
        float w_ = (lane & 1) ? px : py;
        u += __shfl_xor_sync(0xffffffffu, w_, 1);          // full px (even) / py (odd)
        const float pv = __shfl_xor_sync(0xffffffffu, u, 1);
        const int r = warp * 128 + s * 16 + rrow;
        if (!(lane & 1) && r + 1 < TT) sv[r + 1] = make_float2(u, pv);

        __syncwarp();                        // slot fully consumed before reuse
        if (s + 2 < NST) issue(s + 2);
        asm volatile("cp.async.commit_group;" ::: "memory");  // uniform group count
    }
    __syncthreads();                         // publish sv across warps

    // ---------------- Phase B: chunked affine scan ----------------
    const float a00 = __ldg(&W[0]),  a01 = __ldg(&W[1]);
    const float a10 = __ldg(&W[34]), a11 = __ldg(&W[35]);

    float4* svp = reinterpret_cast<float4*>(sv) + tid * 2;

    // serial inclusive scan of the 4-chunk; park results back into smem
    float2 s2;
    {
        const float4 c0 = svp[0], c1 = svp[1];
        s2 = make_float2(c0.x, c0.y);
        float s1x = fmaf(a00, s2.x, fmaf(a01, s2.y, c0.z));
        float s1y = fmaf(a10, s2.x, fmaf(a11, s2.y, c0.w));
        float s2x = fmaf(a00, s1x, fmaf(a01, s1y, c1.x));
        float s2y = fmaf(a10, s1x, fmaf(a11, s1y, c1.y));
        float s3x = fmaf(a00, s2x, fmaf(a01, s2y, c1.z));
        float s3y = fmaf(a10, s2x, fmaf(a11, s2y, c1.w));
        svp[0] = make_float4(s2.x, s2.y, s1x, s1y);
        svp[1] = make_float4(s2x, s2y, s3x, s3y);
        s2 = make_float2(s3x, s3y);
    }

    // A -> A^4 (2 squarings)
    float p00 = a00, p01 = a01, p10 = a10, p11 = a11;
    #pragma unroll
    for (int i = 0; i < 2; ++i) {
        float q00 = p00*p00 + p01*p10, q01 = p00*p01 + p01*p11;
        float q10 = p10*p00 + p11*p10, q11 = p10*p01 + p11*p11;
        p00 = q00; p01 = q01; p10 = q10; p11 = q11;
    }

    // warp shuffle scan of chunk aggregates; powers A^(4*2^d)
    float2 x = s2;
    #pragma unroll
    for (int d = 0; d < 5; ++d) {
        if (tid == 0) { sPW[d][0] = p00; sPW[d][1] = p01; sPW[d][2] = p10; sPW[d][3] = p11; }
        const int o = 1 << d;
        float ox = __shfl_up_sync(0xffffffffu, x.x, o);
        float oy = __shfl_up_sync(0xffffffffu, x.y, o);
        if (lane >= o) {
            x.x = fmaf(p00, ox, fmaf(p01, oy, x.x));
            x.y = fmaf(p10, ox, fmaf(p11, oy, x.y));
        }
        float q00 = p00*p00 + p01*p10, q01 = p00*p01 + p01*p11;
        float q10 = p10*p00 + p11*p10, q11 = p10*p01 + p11*p11;
        p00 = q00; p01 = q01; p10 = q10; p11 = q11;
    }
    // p = A^128 (one warp segment)

    if (lane == 31) agg[warp] = x;
    __syncthreads();   // publishes agg, sPW, parked chunk scans

    // prefix over earlier warps (combine power A^128), <=7 serial steps
    float2 P = make_float2(0.f, 0.f);
    for (int u = 0; u < warp; ++u) {
        float nx = fmaf(p00, P.x, fmaf(p01, P.y, agg[u].x));
        float ny = fmaf(p10, P.x, fmaf(p11, P.y, agg[u].y));
        P.x = nx; P.y = ny;
    }

    // exclusive lane prefix within warp
    float Ex = __shfl_up_sync(0xffffffffu, x.x, 1);
    float Ey = __shfl_up_sync(0xffffffffu, x.y, 1);
    if (lane == 0) { Ex = 0.f; Ey = 0.f; }

    // M = A^(4*lane) from shared power table
    float m00 = 1.f, m01 = 0.f, m10 = 0.f, m11 = 1.f;
    #pragma unroll
    for (int d = 0; d < 5; ++d) {
        if (lane & (1 << d)) {
            const float v0 = sPW[d][0], v1 = sPW[d][1];
            const float v2 = sPW[d][2], v3 = sPW[d][3];
            float n00 = v0*m00 + v1*m10, n01 = v0*m01 + v1*m11;
            float n10 = v2*m00 + v3*m10, n11 = v2*m01 + v3*m11;
            m00 = n00; m01 = n01; m10 = n10; m11 = n11;
        }
    }
    const float bx = Ex + m00 * P.x + m01 * P.y;
    const float by = Ey + m10 * P.x + m11 * P.y;

    // carry fixup on reload + coalesced streaming store
    float cx = fmaf(a00, bx, a01 * by);
    float cy = fmaf(a10, bx, a11 * by);
    const float4 r0 = svp[0], r1 = svp[1];
    float4 o0, o1;
    o0.x = r0.x + cx;  o0.y = r0.y + cy;
    { float nx = fmaf(a00, cx, a01 * cy), ny = fmaf(a10, cx, a11 * cy); cx = nx; cy = ny; }
    o0.z = r0.z + cx;  o0.w = r0.w + cy;
    { float nx = fmaf(a00, cx, a01 * cy), ny = fmaf(a10, cx, a11 * cy); cx = nx; cy = ny; }
    o1.x = r1.x + cx;  o1.y = r1.y + cy;
    { float nx = fmaf(a00, cx, a01 * cy), ny = fmaf(a10, cx, a11 * cy); cx = nx; cy = ny; }
    o1.z = r1.z + cx;  o1.w = r1.w + cy;

    float4* op = reinterpret_cast<float4*>(out) + ((size_t)b * TT / 2) + tid * 2;
    __stcs(op,     o0);
    __stcs(op + 1, o1);
}

extern "C" void kernel_launch(void* const* d_in, const int* in_sizes, int n_in,
                              void* d_out, int out_size) {
    const float* init_states = (const float*)d_in[0];
    const float* z           = (const float*)d_in[1];
    const float* W           = (const float*)d_in[2];
    float*       out         = (float*)d_out;

    fused_decoder_kernel<<<BB, 256>>>(init_states, z, W, out);
}